// round 1
// baseline (speedup 1.0000x reference)
#include <cuda_runtime.h>
#include <math.h>

#define NTAGS 32
#define SLEN 512
#define START_TAG 30
#define STOP_TAG 31
#define WARPS_PER_CTA 4
#define CTA_THREADS (WARPS_PER_CTA * 32)

typedef unsigned long long u64;

__device__ __forceinline__ u64 pack2(float a, float b) {
    u64 r;
    asm("mov.b64 %0, {%1, %2};" : "=l"(r) : "f"(a), "f"(b));
    return r;
}
__device__ __forceinline__ void unpack2(u64 v, float &a, float &b) {
    asm("mov.b64 {%0, %1}, %2;" : "=f"(a), "=f"(b) : "l"(v));
}
__device__ __forceinline__ u64 fma2(u64 a, u64 b, u64 c) {
    u64 d;
    asm("fma.rn.f32x2 %0, %1, %2, %3;" : "=l"(d) : "l"(a), "l"(b), "l"(c));
    return d;
}
__device__ __forceinline__ u64 add2(u64 a, u64 b) {
    u64 d;
    asm("add.rn.f32x2 %0, %1, %2;" : "=l"(d) : "l"(a), "l"(b));
    return d;
}
__device__ __forceinline__ u64 mul2(u64 a, u64 b) {
    u64 d;
    asm("mul.rn.f32x2 %0, %1, %2;" : "=l"(d) : "l"(a), "l"(b));
    return d;
}

// One warp handles TWO batches (packed f32x2). Lane i owns tag i.
// State kept in exp-domain: w = exp(alpha - esum*ln2). E = exp(transitions)
// row i lives in lane i's registers, duplicated into both f32x2 halves.
// Per step: broadcast w via 128B smem ping-pong, 32 packed FMAs (matvec),
// multiply by exp(emission). Renormalize every 4 steps by an exact power
// of two (exponent extraction -> integer accumulator, zero rounding).
__global__ __launch_bounds__(CTA_THREADS)
void crf_fwd_kernel(const float* __restrict__ feats,
                    const float* __restrict__ trans,
                    float* __restrict__ out, int nwarps) {
    __shared__ __align__(16) float wbuf[WARPS_PER_CTA][2][NTAGS * 2];
    const int lane = threadIdx.x & 31;
    const int wip  = threadIdx.x >> 5;
    const int gw   = blockIdx.x * WARPS_PER_CTA + wip;
    if (gw >= nwarps) return;
    const int b0 = gw * 2, b1 = gw * 2 + 1;

    // E row for target tag i = lane (duplicated into both packed halves)
    u64 E2[NTAGS];
#pragma unroll
    for (int j = 0; j < NTAGS; j++) {
        float e = __expf(trans[lane * NTAGS + j]);
        E2[j] = pack2(e, e);
    }
    const float eStop = __expf(trans[STOP_TAG * NTAGS + lane]);

    const float* p0 = feats + (size_t)b0 * SLEN * NTAGS + lane;
    const float* p1 = feats + (size_t)b1 * SLEN * NTAGS + lane;

    // init: alpha one-hot at START  ->  w one-hot
    const float w0 = (lane == START_TAG) ? 1.0f : 0.0f;
    *reinterpret_cast<float2*>(&wbuf[wip][0][lane * 2]) = make_float2(w0, w0);
    __syncwarp();

    int esum0 = 0, esum1 = 0;
    float em0 = p0[0], em1 = p1[0];
    u64 next = 0;

#pragma unroll 4
    for (int t = 0; t < SLEN; t++) {
        // prefetch next step's emissions (clamped to stay in-bounds at t=S-1)
        const int tn = (t + 1 < SLEN) ? (t + 1) : (SLEN - 1);
        const float em0n = p0[tn * NTAGS];
        const float em1n = p1[tn * NTAGS];
        const float pe0 = __expf(em0);
        const float pe1 = __expf(em1);

        // matvec: next_i = sum_j w_j * E[i,j]  (packed over 2 batches)
        const float* buf = wbuf[wip][t & 1];
        u64 a0 = 0, a1 = 0, a2 = 0, a3 = 0;
#pragma unroll
        for (int jj = 0; jj < 8; jj++) {
            ulonglong2 va = *reinterpret_cast<const ulonglong2*>(buf + 8 * jj);
            ulonglong2 vb = *reinterpret_cast<const ulonglong2*>(buf + 8 * jj + 4);
            a0 = fma2(va.x, E2[4 * jj + 0], a0);
            a1 = fma2(va.y, E2[4 * jj + 1], a1);
            a2 = fma2(vb.x, E2[4 * jj + 2], a2);
            a3 = fma2(vb.y, E2[4 * jj + 3], a3);
        }
        next = mul2(add2(add2(a0, a1), add2(a2, a3)), pack2(pe0, pe1));

        // renormalize every 4 steps (branch folds under unroll-4):
        // max growth/step <= 32*max(E)*max(e^emit) ~ e^13 => 4 steps < e^52, safe in fp32.
        if ((t & 3) == 3) {
            float n0, n1;
            unpack2(next, n0, n1);
            float m0 = n0, m1 = n1;
#pragma unroll
            for (int k = 16; k; k >>= 1) {
                m0 = fmaxf(m0, __shfl_xor_sync(0xffffffffu, m0, k));
                m1 = fmaxf(m1, __shfl_xor_sync(0xffffffffu, m1, k));
            }
            const int e0 = (__float_as_int(m0) >> 23) - 127;
            const int e1 = (__float_as_int(m1) >> 23) - 127;
            esum0 += e0; esum1 += e1;
            const float s0 = __int_as_float((127 - e0) << 23);  // exact 2^-e
            const float s1 = __int_as_float((127 - e1) << 23);
            next = mul2(next, pack2(s0, s1));
        }

        {
            float n0, n1;
            unpack2(next, n0, n1);
            *reinterpret_cast<float2*>(&wbuf[wip][(t + 1) & 1][lane * 2]) =
                make_float2(n0, n1);
        }
        __syncwarp();
        em0 = em0n; em1 = em1n;
    }

    // terminate: logZ = esum*ln2 + log( sum_j w_j * exp(T[STOP,j]) )
    u64 term = mul2(next, pack2(eStop, eStop));
    float s0, s1;
    unpack2(term, s0, s1);
#pragma unroll
    for (int k = 16; k; k >>= 1) {
        s0 += __shfl_xor_sync(0xffffffffu, s0, k);
        s1 += __shfl_xor_sync(0xffffffffu, s1, k);
    }
    if (lane == 0) {
        out[b0] = (float)((double)esum0 * 0.6931471805599453 + log((double)s0));
        out[b1] = (float)((double)esum1 * 0.6931471805599453 + log((double)s1));
    }
}

extern "C" void kernel_launch(void* const* d_in, const int* in_sizes, int n_in,
                              void* d_out, int out_size) {
    const float* feats = (const float*)d_in[0];
    const float* trans = (const float*)d_in[1];
    float* out = (float*)d_out;
    const int B = in_sizes[0] / (SLEN * NTAGS);
    const int nwarps = B / 2;  // 2 batches per warp (f32x2 packing)
    const int nblocks = (nwarps + WARPS_PER_CTA - 1) / WARPS_PER_CTA;
    crf_fwd_kernel<<<nblocks, CTA_THREADS>>>(feats, trans, out, nwarps);
}

// round 3
// speedup vs baseline: 1.6663x; 1.6663x over previous
#include <cuda_runtime.h>
#include <math.h>

#define NTAGS 32
#define SLEN 512
#define START_TAG 30
#define STOP_TAG 31

typedef unsigned long long u64;

__device__ __forceinline__ u64 pack2(float a, float b) {
    u64 r;
    asm("mov.b64 %0, {%1, %2};" : "=l"(r) : "f"(a), "f"(b));
    return r;
}
__device__ __forceinline__ void unpack2(u64 v, float &a, float &b) {
    asm("mov.b64 {%0, %1}, %2;" : "=f"(a), "=f"(b) : "l"(v));
}
__device__ __forceinline__ u64 fma2(u64 a, u64 b, u64 c) {
    u64 d;
    asm("fma.rn.f32x2 %0, %1, %2, %3;" : "=l"(d) : "l"(a), "l"(b), "l"(c));
    return d;
}
__device__ __forceinline__ u64 add2(u64 a, u64 b) {
    u64 d;
    asm("add.rn.f32x2 %0, %1, %2;" : "=l"(d) : "l"(a), "l"(b));
    return d;
}
__device__ __forceinline__ u64 mul2(u64 a, u64 b) {
    u64 d;
    asm("mul.rn.f32x2 %0, %1, %2;" : "=l"(d) : "l"(a), "l"(b));
    return d;
}

// One warp (= one 32-thread CTA) handles TWO batches packed as f32x2.
// Lane i owns target-tag i; exp(transitions) row i lives in lane i's regs.
// Exp-domain recurrence w' = (E @ w) * exp(emit), renormalized every 4 steps
// by an exact power of two (exponent extraction, integer scale accumulator).
// Emissions are prefetched a FULL 4-step block ahead (8 outstanding LDGs) so
// DRAM latency never paces the serial recurrence; exp(emit) for the whole
// block is computed at block top, off the critical chain.
__global__ __launch_bounds__(32)
void crf_fwd_kernel(const float* __restrict__ feats,
                    const float* __restrict__ trans,
                    float* __restrict__ out) {
    __shared__ __align__(16) float wbuf[2][NTAGS * 2];
    const int lane = threadIdx.x;
    const int gw = blockIdx.x;
    const int b0 = gw * 2, b1 = b0 + 1;

    u64 E2[NTAGS];
#pragma unroll
    for (int j = 0; j < NTAGS; j++) {
        float e = __expf(trans[lane * NTAGS + j]);
        E2[j] = pack2(e, e);
    }
    const float eStop = __expf(trans[STOP_TAG * NTAGS + lane]);

    const float* p0 = feats + (size_t)b0 * SLEN * NTAGS + lane;
    const float* p1 = feats + (size_t)b1 * SLEN * NTAGS + lane;

    // init: alpha one-hot at START -> w one-hot
    const float winit = (lane == START_TAG) ? 1.0f : 0.0f;
    *reinterpret_cast<float2*>(&wbuf[0][lane * 2]) = make_float2(winit, winit);
    __syncwarp();

    int esum0 = 0, esum1 = 0;
    float em0[4], em1[4];
#pragma unroll
    for (int u = 0; u < 4; u++) {
        em0[u] = p0[u * NTAGS];
        em1[u] = p1[u * NTAGS];
    }
    u64 next = 0;
    int cur = 0;

    for (int tb = 0; tb < SLEN; tb += 4) {
        // Prefetch NEXT block's emissions (8 independent LDGs, ~4 steps of slack)
        float nx0[4], nx1[4];
        const int nb = (tb + 4 < SLEN) ? (tb + 4) : (SLEN - 4);
#pragma unroll
        for (int u = 0; u < 4; u++) {
            nx0[u] = p0[(nb + u) * NTAGS];
            nx1[u] = p1[(nb + u) * NTAGS];
        }
        // exp of THIS block's emissions (loaded a block ago) — MUFU off-chain
        float pe0[4], pe1[4];
#pragma unroll
        for (int u = 0; u < 4; u++) {
            pe0[u] = __expf(em0[u]);
            pe1[u] = __expf(em1[u]);
        }
#pragma unroll
        for (int u = 0; u < 4; u++) {
            const float* buf = wbuf[cur];
            u64 a0 = 0, a1 = 0, a2 = 0, a3 = 0;
#pragma unroll
            for (int jj = 0; jj < 8; jj++) {
                ulonglong2 va = *reinterpret_cast<const ulonglong2*>(buf + 8 * jj);
                ulonglong2 vb = *reinterpret_cast<const ulonglong2*>(buf + 8 * jj + 4);
                a0 = fma2(va.x, E2[4 * jj + 0], a0);
                a1 = fma2(va.y, E2[4 * jj + 1], a1);
                a2 = fma2(vb.x, E2[4 * jj + 2], a2);
                a3 = fma2(vb.y, E2[4 * jj + 3], a3);
            }
            next = mul2(add2(add2(a0, a1), add2(a2, a3)), pack2(pe0[u], pe1[u]));
            float n0, n1;
            unpack2(next, n0, n1);
            if (u == 3) {
                // power-of-2 renorm. w >= 0, so the IEEE bit pattern is
                // monotone as signed int: integer redux.max == float max.
                int m0i, m1i;
                asm("redux.sync.max.s32 %0, %1, 0xffffffff;"
                    : "=r"(m0i) : "r"(__float_as_int(n0)));
                asm("redux.sync.max.s32 %0, %1, 0xffffffff;"
                    : "=r"(m1i) : "r"(__float_as_int(n1)));
                const int e0 = (m0i >> 23) - 127;
                const int e1 = (m1i >> 23) - 127;
                esum0 += e0; esum1 += e1;
                n0 *= __int_as_float((127 - e0) << 23);  // exact 2^-e0
                n1 *= __int_as_float((127 - e1) << 23);
            }
            *reinterpret_cast<float2*>(&wbuf[cur ^ 1][lane * 2]) =
                make_float2(n0, n1);
            __syncwarp();
            if (u == 3) next = pack2(n0, n1);
            cur ^= 1;
        }
#pragma unroll
        for (int u = 0; u < 4; u++) { em0[u] = nx0[u]; em1[u] = nx1[u]; }
    }

    // terminate: logZ = esum*ln2 + log( sum_j w_j * exp(T[STOP,j]) )
    float s0, s1;
    unpack2(next, s0, s1);
    s0 *= eStop;
    s1 *= eStop;
#pragma unroll
    for (int k = 16; k; k >>= 1) {
        s0 += __shfl_xor_sync(0xffffffffu, s0, k);
        s1 += __shfl_xor_sync(0xffffffffu, s1, k);
    }
    if (lane == 0) {
        out[b0] = (float)((double)esum0 * 0.6931471805599453 + log((double)s0));
        out[b1] = (float)((double)esum1 * 0.6931471805599453 + log((double)s1));
    }
}

extern "C" void kernel_launch(void* const* d_in, const int* in_sizes, int n_in,
                              void* d_out, int out_size) {
    const float* feats = (const float*)d_in[0];
    const float* trans = (const float*)d_in[1];
    float* out = (float*)d_out;
    const int B = in_sizes[0] / (SLEN * NTAGS);
    const int nblocks = B / 2;  // one 32-thread CTA (one warp) per 2 batches
    crf_fwd_kernel<<<nblocks, 32>>>(feats, trans, out);
}

// round 4
// speedup vs baseline: 1.9290x; 1.1576x over previous
#include <cuda_runtime.h>
#include <math.h>

#define NTAGS 32
#define SLEN 512
#define START_TAG 30
#define STOP_TAG 31

// One warp (= one 32-thread CTA) handles ONE batch. Lane i owns target-tag i;
// exp(transitions) row i lives in lane i's registers (32 scalars).
// Exp-domain recurrence w' = (E @ w) * exp(emit); renormalized every 4 steps
// by an exact power of two (exponent extraction -> integer accumulator).
// Emissions are prefetched TWO 4-step blocks ahead (~1500 cyc slack >> 577 cyc
// DRAM latency) so the serial recurrence is never paced by memory. 2048 warps
// (3.46/SMSP) make the kernel issue-limited rather than stall-limited.
__global__ __launch_bounds__(32)
void crf_fwd_kernel(const float* __restrict__ feats,
                    const float* __restrict__ trans,
                    float* __restrict__ out) {
    __shared__ __align__(16) float wbuf[2][NTAGS];
    const int lane = threadIdx.x;
    const int b = blockIdx.x;

    float E[NTAGS];
#pragma unroll
    for (int j = 0; j < NTAGS; j++)
        E[j] = __expf(trans[lane * NTAGS + j]);
    const float eStop = __expf(trans[STOP_TAG * NTAGS + lane]);

    const float* p = feats + (size_t)b * SLEN * NTAGS + lane;

    // init: alpha one-hot at START -> w one-hot
    wbuf[0][lane] = (lane == START_TAG) ? 1.0f : 0.0f;
    __syncwarp();

    int esum = 0;
    // two-block-deep emission pipeline: emA = block tb, emB = block tb+4
    float emA[4], emB[4];
#pragma unroll
    for (int u = 0; u < 4; u++) {
        emA[u] = p[u * NTAGS];
        emB[u] = p[(4 + u) * NTAGS];
    }
    float nextv = 0.0f;
    int cur = 0;

    for (int tb = 0; tb < SLEN; tb += 4) {
        // issue LDGs for block tb+8 (consumed two blocks from now)
        float nx[4];
        const int nb = (tb + 8 < SLEN) ? (tb + 8) : (SLEN - 4);
#pragma unroll
        for (int u = 0; u < 4; u++)
            nx[u] = p[(nb + u) * NTAGS];

        // exp of THIS block's emissions (loaded two blocks ago) — off-chain
        float pe[4];
#pragma unroll
        for (int u = 0; u < 4; u++)
            pe[u] = __expf(emA[u]);

#pragma unroll
        for (int u = 0; u < 4; u++) {
            const float4* buf4 = reinterpret_cast<const float4*>(wbuf[cur]);
            float a0 = 0.f, a1 = 0.f, a2 = 0.f, a3 = 0.f;
#pragma unroll
            for (int jj = 0; jj < 8; jj++) {
                const float4 v = buf4[jj];
                a0 = fmaf(v.x, E[4 * jj + 0], a0);
                a1 = fmaf(v.y, E[4 * jj + 1], a1);
                a2 = fmaf(v.z, E[4 * jj + 2], a2);
                a3 = fmaf(v.w, E[4 * jj + 3], a3);
            }
            nextv = ((a0 + a1) + (a2 + a3)) * pe[u];
            if (u == 3) {
                // power-of-2 renorm. w >= 0 => IEEE bits monotone as s32,
                // so integer redux.max == float max (sm_103a has no redux.f32)
                int mi;
                asm("redux.sync.max.s32 %0, %1, 0xffffffff;"
                    : "=r"(mi) : "r"(__float_as_int(nextv)));
                const int e = (mi >> 23) - 127;
                esum += e;
                nextv *= __int_as_float((127 - e) << 23);  // exact 2^-e
            }
            wbuf[cur ^ 1][lane] = nextv;
            __syncwarp();
            cur ^= 1;
        }
#pragma unroll
        for (int u = 0; u < 4; u++) { emA[u] = emB[u]; emB[u] = nx[u]; }
    }

    // terminate: logZ = esum*ln2 + log( sum_j w_j * exp(T[STOP,j]) )
    float s = nextv * eStop;
#pragma unroll
    for (int k = 16; k; k >>= 1)
        s += __shfl_xor_sync(0xffffffffu, s, k);
    if (lane == 0)
        out[b] = (float)((double)esum * 0.6931471805599453 + log((double)s));
}

extern "C" void kernel_launch(void* const* d_in, const int* in_sizes, int n_in,
                              void* d_out, int out_size) {
    const float* feats = (const float*)d_in[0];
    const float* trans = (const float*)d_in[1];
    float* out = (float*)d_out;
    const int B = in_sizes[0] / (SLEN * NTAGS);
    crf_fwd_kernel<<<B, 32>>>(feats, trans, out);  // one warp per batch
}